// round 1
// baseline (speedup 1.0000x reference)
#include <cuda_runtime.h>

#define Bb 4
#define Ss 1024
#define Dd 32
#define Hh 32

// scratch: c[b,h] = sum_j softmax_j(K[b,:,h]) * V[b,j,h]
__device__ float g_c[Bb * Hh];

// Kernel 1: one block per (b,h). Online softmax-weighted reduction over j.
__global__ void __launch_bounds__(256) foaa_head_reduce(
    const float* __restrict__ x,
    const float* __restrict__ Wk, const float* __restrict__ bk,
    const float* __restrict__ Wv, const float* __restrict__ bv)
{
    const int b = blockIdx.x >> 5;   // blockIdx.x = b*32 + h
    const int h = blockIdx.x & 31;
    const int tid = threadIdx.x;

    __shared__ float wk[Dd], wv[Dd];
    if (tid < Dd)            wk[tid]      = Wk[h * Dd + tid];
    else if (tid < 2 * Dd)   wv[tid - Dd] = Wv[h * Dd + (tid - Dd)];
    __syncthreads();

    const float bkh = bk[h];
    const float bvh = bv[h];

    float m = -1e30f, s = 0.0f, sv = 0.0f;
    const float* xb = x + (size_t)b * Ss * Dd;

    for (int j = tid; j < Ss; j += 256) {
        const float4* row = (const float4*)(xb + j * Dd);
        float k = bkh, v = bvh;
        #pragma unroll
        for (int q = 0; q < 8; q++) {
            float4 xv = row[q];
            k = fmaf(xv.x, wk[4*q+0], k); k = fmaf(xv.y, wk[4*q+1], k);
            k = fmaf(xv.z, wk[4*q+2], k); k = fmaf(xv.w, wk[4*q+3], k);
            v = fmaf(xv.x, wv[4*q+0], v); v = fmaf(xv.y, wv[4*q+1], v);
            v = fmaf(xv.z, wv[4*q+2], v); v = fmaf(xv.w, wv[4*q+3], v);
        }
        float mn = fmaxf(m, k);
        float scale = __expf(m - mn);
        float e     = __expf(k - mn);
        s  = s * scale + e;
        sv = sv * scale + e * v;
        m = mn;
    }

    // warp-level merge of (m, s, sv)
    #pragma unroll
    for (int off = 16; off; off >>= 1) {
        float m2  = __shfl_xor_sync(0xffffffffu, m,  off);
        float s2  = __shfl_xor_sync(0xffffffffu, s,  off);
        float sv2 = __shfl_xor_sync(0xffffffffu, sv, off);
        float mn = fmaxf(m, m2);
        float a  = __expf(m  - mn);
        float c2 = __expf(m2 - mn);
        s  = s  * a + s2  * c2;
        sv = sv * a + sv2 * c2;
        m = mn;
    }

    __shared__ float sm[8], ss[8], ssv[8];
    const int w = tid >> 5, lane = tid & 31;
    if (lane == 0) { sm[w] = m; ss[w] = s; ssv[w] = sv; }
    __syncthreads();
    if (tid == 0) {
        m = sm[0]; s = ss[0]; sv = ssv[0];
        #pragma unroll
        for (int i = 1; i < 8; i++) {
            float mn = fmaxf(m, sm[i]);
            float a  = __expf(m     - mn);
            float c2 = __expf(sm[i] - mn);
            s  = s  * a + ss[i]  * c2;
            sv = sv * a + ssv[i] * c2;
            m = mn;
        }
        g_c[b * Hh + h] = sv / s;
    }
}

// Kernel 2: y[b,d] = bo[d] + sum_h c[b,h]*Wo[d,h]; broadcast over i.
// grid = (S/64, B); each block writes 64 rows (64*32 floats = 512 float4).
__global__ void __launch_bounds__(256) foaa_out_broadcast(
    const float* __restrict__ Wo, const float* __restrict__ bo,
    float* __restrict__ out)
{
    const int b = blockIdx.y;
    const int tid = threadIdx.x;
    __shared__ float y[Dd];

    if (tid < Dd) {
        float acc = bo[tid];
        #pragma unroll
        for (int hh = 0; hh < Hh; hh++)
            acc = fmaf(g_c[b * Hh + hh], Wo[tid * Dd + hh], acc);
        y[tid] = acc;
    }
    __syncthreads();

    const int i0 = blockIdx.x * 64;
    float4* outp = (float4*)(out + ((size_t)b * Ss + i0) * Dd);
    #pragma unroll
    for (int kk = 0; kk < 2; kk++) {
        int f = tid + kk * 256;                 // float4 index within chunk
        float4 v = *(const float4*)&y[(f * 4) & (Dd - 1)];
        outp[f] = v;
    }
}

extern "C" void kernel_launch(void* const* d_in, const int* in_sizes, int n_in,
                              void* d_out, int out_size)
{
    // metadata order: x, Wq, bq, Wk, bk, Wv, bv, Wo, bo
    const float* x  = (const float*)d_in[0];
    const float* Wk = (const float*)d_in[3];
    const float* bk = (const float*)d_in[4];
    const float* Wv = (const float*)d_in[5];
    const float* bv = (const float*)d_in[6];
    const float* Wo = (const float*)d_in[7];
    const float* bo = (const float*)d_in[8];
    float* out = (float*)d_out;

    foaa_head_reduce<<<Bb * Hh, 256>>>(x, Wk, bk, Wv, bv);
    foaa_out_broadcast<<<dim3(Ss / 64, Bb), 256>>>(Wo, bo, out);
}